// round 3
// baseline (speedup 1.0000x reference)
#include <cuda_runtime.h>
#include <cuda_bf16.h>

// STSEarlyFusionConcat: out (1, 2C, D, H, W) fp32
//   out[c,d,h,w]    = (w>=d) ? x[c,h,w]   : 0    for c in [0,C)
//   out[C+c,d,h,w]  = (w>=d) ? y[c,h,w-d] : 0    for c in [0,C)
// B=1, C=32, H=96, W=192, D=64.  HBM-write-bound: 302 MB out.
// R3: 8 consecutive d-values per thread:
//   x: 1 LDG.128 -> 8 masked STG.128
//   y: 11 predicated scalar loads cover all 8 shifted windows

namespace {
constexpr int C   = 32;
constexpr int H   = 96;
constexpr int W   = 192;
constexpr int D   = 64;
constexpr int W4  = W / 4;                 // 48
constexpr int DO  = D / 8;                 // 8 d-octets
constexpr long long NTHREADS = (long long)(2 * C) * DO * H * W4;  // 2,359,296
}

__global__ __launch_bounds__(256)
void stsef_kernel(const float* __restrict__ x,
                  const float* __restrict__ y,
                  float4* __restrict__ out)
{
    unsigned idx = blockIdx.x * blockDim.x + threadIdx.x;
    // idx = ((c2*DO + dq)*H + h)*W4 + w4
    unsigned w4 = idx % W4;
    unsigned t  = idx / W4;
    unsigned h  = t % H;   t /= H;
    unsigned dq = t % DO;  t /= DO;
    unsigned c2 = t;                        // 0..63

    int w0 = (int)(w4 * 4);
    int d0 = (int)(dq * 8);

    size_t obase = (((size_t)(c2 * D + d0) * H) + h) * W4 + w4;  // float4 index
    const size_t dstr = (size_t)H * W4;                          // stride per d

    if (c2 < C) {
        // cost_x: one aligned vector load, 8 masked streaming stores
        const float4* xr = reinterpret_cast<const float4*>(x + ((c2 * H) + h) * W);
        float4 xv = __ldg(xr + w4);
#pragma unroll
        for (int k = 0; k < 8; k++) {
            int dd = d0 + k;
            float4 v;
            v.x = (w0 + 0 >= dd) ? xv.x : 0.0f;
            v.y = (w0 + 1 >= dd) ? xv.y : 0.0f;
            v.z = (w0 + 2 >= dd) ? xv.z : 0.0f;
            v.w = (w0 + 3 >= dd) ? xv.w : 0.0f;
            __stcs(out + obase + (size_t)k * dstr, v);
        }
    } else {
        // cost_y: 11 scalars y[b-7 .. b+3] (b = w0-d0) cover the 8 shifted windows.
        // Load predicate (e >= 0) doubles as the validity mask.
        const float* yr = y + (((c2 - C) * H) + h) * W;
        int b = w0 - d0;
        float tv[11];
#pragma unroll
        for (int i = 0; i < 11; i++) {
            int e = b - 7 + i;
            tv[i] = (e >= 0) ? __ldg(yr + e) : 0.0f;
        }
#pragma unroll
        for (int k = 0; k < 8; k++) {
            // component j of store k = y[b + j - k] = tv[7 + j - k]
            float4 v;
            v.x = tv[7 - k];
            v.y = tv[8 - k];
            v.z = tv[9 - k];
            v.w = tv[10 - k];
            __stcs(out + obase + (size_t)k * dstr, v);
        }
    }
}

extern "C" void kernel_launch(void* const* d_in, const int* in_sizes, int n_in,
                              void* d_out, int out_size)
{
    const float* x = (const float*)d_in[0];
    const float* y = (const float*)d_in[1];
    float4* out = (float4*)d_out;

    const int threads = 256;
    const unsigned blocks = (unsigned)(NTHREADS / threads);  // 9,216
    stsef_kernel<<<blocks, threads>>>(x, y, out);
}